// round 16
// baseline (speedup 1.0000x reference)
#include <cuda_runtime.h>
#include <cuda_bf16.h>

// ---------------------------------------------------------------------------
// DiffJPEG: out = x + (jpeg75(clip(x,0,1)) - x), x: [16,3,512,512] fp32
// Fused single kernel. CTA = 32x32 pixel tile, 256 threads, 5 CTAs/SM.
// R16: DCT blocks fully register-resident. Column load (8 LDS) -> D*X with
//      uniform const D -> shfl transpose -> K row + quantize (8 LDS q-row)
//      -> S row -> shfl transpose -> rec column -> 8 STS. No st/st2 smem.
// ---------------------------------------------------------------------------

// DCT-II matrix D[u][x] = 0.5*cos((2x+1)u*pi/16), row 0 scaled by 1/sqrt(2).
__constant__ float cD[64] = {
    0.3535533906f,  0.3535533906f,  0.3535533906f,  0.3535533906f,
    0.3535533906f,  0.3535533906f,  0.3535533906f,  0.3535533906f,
    0.4903926402f,  0.4157348062f,  0.2777851165f,  0.0975451610f,
   -0.0975451610f, -0.2777851165f, -0.4157348062f, -0.4903926402f,
    0.4619397663f,  0.1913417162f, -0.1913417162f, -0.4619397663f,
   -0.4619397663f, -0.1913417162f,  0.1913417162f,  0.4619397663f,
    0.4157348062f, -0.0975451610f, -0.4903926402f, -0.2777851165f,
    0.2777851165f,  0.4903926402f,  0.0975451610f, -0.4157348062f,
    0.3535533906f, -0.3535533906f, -0.3535533906f,  0.3535533906f,
    0.3535533906f, -0.3535533906f, -0.3535533906f,  0.3535533906f,
    0.2777851165f, -0.4903926402f,  0.0975451610f,  0.4157348062f,
   -0.4157348062f, -0.0975451610f,  0.4903926402f, -0.2777851165f,
    0.1913417162f, -0.4619397663f,  0.4619397663f, -0.1913417162f,
   -0.1913417162f,  0.4619397663f, -0.4619397663f,  0.1913417162f,
    0.0975451610f, -0.2777851165f,  0.4157348062f, -0.4903926402f,
    0.4903926402f, -0.4157348062f,  0.2777851165f, -0.0975451610f
};

// Quant tables pre-multiplied by factor = (200 - 2*75)/100 = 0.5 (exact in fp32)
__constant__ float cQY[64] = {
     8.0f,  5.5f,  5.0f,  8.0f, 12.0f, 20.0f, 25.5f, 30.5f,
     6.0f,  6.0f,  7.0f,  9.5f, 13.0f, 29.0f, 30.0f, 27.5f,
     7.0f,  6.5f,  8.0f, 12.0f, 20.0f, 28.5f, 34.5f, 28.0f,
     7.0f,  8.5f, 11.0f, 14.5f, 25.5f, 43.5f, 40.0f, 31.0f,
     9.0f, 11.0f, 18.5f, 28.0f, 34.0f, 54.5f, 51.5f, 38.5f,
    12.0f, 17.5f, 27.5f, 32.0f, 40.5f, 52.0f, 56.5f, 46.0f,
    24.5f, 32.0f, 39.0f, 43.5f, 51.5f, 60.5f, 60.0f, 50.5f,
    36.0f, 46.0f, 47.5f, 49.0f, 56.0f, 50.0f, 51.5f, 49.5f
};
__constant__ float cQC[64] = {
     8.5f,  9.0f, 12.0f, 23.5f, 49.5f, 49.5f, 49.5f, 49.5f,
     9.0f, 10.5f, 13.0f, 33.0f, 49.5f, 49.5f, 49.5f, 49.5f,
    12.0f, 13.0f, 28.0f, 49.5f, 49.5f, 49.5f, 49.5f, 49.5f,
    23.5f, 33.0f, 49.5f, 49.5f, 49.5f, 49.5f, 49.5f, 49.5f,
    49.5f, 49.5f, 49.5f, 49.5f, 49.5f, 49.5f, 49.5f, 49.5f,
    49.5f, 49.5f, 49.5f, 49.5f, 49.5f, 49.5f, 49.5f, 49.5f,
    49.5f, 49.5f, 49.5f, 49.5f, 49.5f, 49.5f, 49.5f, 49.5f,
    49.5f, 49.5f, 49.5f, 49.5f, 49.5f, 49.5f, 49.5f, 49.5f
};

#define IMG 512

// 8x8 transpose across the 8 lanes of a group (lane = low 3 bits).
// After: reg j of lane i = original reg i of lane j.
__device__ __forceinline__ void transpose8(float a[8], int lane3)
{
    #pragma unroll
    for (int m = 1; m < 8; m <<= 1) {
        const bool upper = (lane3 & m) != 0;
        #pragma unroll
        for (int j = 0; j < 8; j++) {
            if ((j & m) == 0) {
                float send = upper ? a[j] : a[j | m];
                float recv = __shfl_xor_sync(0xffffffffu, send, m);
                if (upper) a[j] = recv; else a[j | m] = recv;
            }
        }
    }
}

__global__ void __launch_bounds__(256, 5)
diffjpeg_kernel(const float* __restrict__ in, float* __restrict__ out)
{
    __shared__ __align__(16) float sy  [32][36];  // Y: input then reconstructed
    __shared__ __align__(16) float scb2[16][20];  // subsampled Cb: in then rec
    __shared__ __align__(16) float scr2[16][20];  // subsampled Cr: in then rec
    __shared__ float sQY [72];   // quant Y, stride 9 (lane-varying row reads)
    __shared__ float sQC [72];   // quant C, stride 9

    const int t    = threadIdx.x;
    const int row  = t >> 3;          // 0..31
    const int col0 = (t & 7) << 2;    // 0,4,...,28

    const int b  = blockIdx.z;
    const int gy = blockIdx.y * 32 + row;
    const int gx = blockIdx.x * 32 + col0;

    const size_t plane = (size_t)IMG * IMG;
    const size_t base  = ((size_t)b * 3) * plane + (size_t)gy * IMG + gx;

    // ---------- Quant-table copy to shared (stride 9) ----------
    if (t < 128) {
        int e   = t & 63;
        int dst = (e >> 3) * 9 + (e & 7);
        if (t < 64) sQY[dst] = cQY[e];
        else        sQC[dst] = cQC[e];
    }

    // ---------- Phase A: load, clip, *255, RGB->YCbCr, chroma 2x2 mean ----
    {
        const float4 xr4 = *(const float4*)(in + base);
        const float4 xg4 = *(const float4*)(in + base + plane);
        const float4 xb4 = *(const float4*)(in + base + 2 * plane);
        float xr[4] = {xr4.x, xr4.y, xr4.z, xr4.w};
        float xg[4] = {xg4.x, xg4.y, xg4.z, xg4.w};
        float xb[4] = {xb4.x, xb4.y, xb4.z, xb4.w};
        float ya[4], cba[4], cra[4];
        #pragma unroll
        for (int i = 0; i < 4; i++) {
            float R = fminf(fmaxf(xr[i], 0.f), 1.f) * 255.f;
            float G = fminf(fmaxf(xg[i], 0.f), 1.f) * 255.f;
            float B = fminf(fmaxf(xb[i], 0.f), 1.f) * 255.f;
            ya [i] =  0.299f    * R + 0.587f    * G + 0.114f    * B;
            cba[i] = -0.168736f * R - 0.331264f * G + 0.5f      * B + 128.f;
            cra[i] =  0.5f      * R - 0.418688f * G - 0.081312f * B + 128.f;
        }
        *(float4*)&sy[row][col0] = make_float4(ya[0], ya[1], ya[2], ya[3]);

        // Horizontal pair sums, then vertical partner via shfl.xor(8)
        float cbh0 = cba[0] + cba[1], cbh1 = cba[2] + cba[3];
        float crh0 = cra[0] + cra[1], crh1 = cra[2] + cra[3];
        float cbo0 = __shfl_xor_sync(0xffffffffu, cbh0, 8);
        float cbo1 = __shfl_xor_sync(0xffffffffu, cbh1, 8);
        float cro0 = __shfl_xor_sync(0xffffffffu, crh0, 8);
        float cro1 = __shfl_xor_sync(0xffffffffu, crh1, 8);
        if (!(row & 1)) {
            int r2 = row >> 1, c2 = col0 >> 1;
            *(float2*)&scb2[r2][c2] =
                make_float2(0.25f * (cbh0 + cbo0), 0.25f * (cbh1 + cbo1));
            *(float2*)&scr2[r2][c2] =
                make_float2(0.25f * (crh0 + cro0), 0.25f * (crh1 + cro1));
        }
    }
    __syncthreads();

    // 24 blocks: 0..15 Y (4x4 grid), 16..19 Cb (2x2), 20..23 Cr (2x2)
    const int bi = t >> 3;      // block id (valid for t < 192)
    const int r  = t & 7;       // lane index within the 8-lane group

    if (t < 192) {
        int br0, bc;

        // ---------- Load block column r: lane r holds X[0..7][r] ----------
        float a[8];
        if (bi < 16) {
            br0 = (bi >> 2) * 8;
            bc  = (bi & 3) * 8;
            #pragma unroll
            for (int i = 0; i < 8; i++) a[i] = sy[br0 + i][bc + r] - 128.f;
        } else {
            const int cj = (bi < 20) ? (bi - 16) : (bi - 20);
            const float (*scs)[20] = (bi < 20) ? scb2 : scr2;
            br0 = (cj >> 1) * 8;
            bc  = (cj & 1) * 8;
            #pragma unroll
            for (int i = 0; i < 8; i++) a[i] = scs[br0 + i][bc + r] - 128.f;
        }

        // ---------- P[u][r] = sum_x D[u][x] * X[x][r]  (uniform D, LDC) ----
        float p[8];
        #pragma unroll
        for (int u = 0; u < 8; u++) {
            float s = 0.f;
            #pragma unroll
            for (int x = 0; x < 8; x++) s += cD[u * 8 + x] * a[x];
            p[u] = s;
        }

        // ---------- T1: lane u now holds P[u][0..7] ----------
        transpose8(p, r);

        // ---------- K[u][v] = sum_y P[u][y] * D[v][y]  (uniform D) --------
        float k[8];
        #pragma unroll
        for (int v = 0; v < 8; v++) {
            float s = 0.f;
            #pragma unroll
            for (int y = 0; y < 8; y++) s += p[y] * cD[v * 8 + y];
            k[v] = s;
        }

        // ---------- Quantize (lane u = r reads q row u, stride 9) ---------
        const float* qs = (bi < 16) ? sQY : sQC;
        #pragma unroll
        for (int v = 0; v < 8; v++) {
            float qq = qs[r * 9 + v];
            k[v] = rintf(k[v] / qq) * qq;         // round-half-even, true div
        }

        // ---------- S[u][y] = sum_v K[u][v] * D[v][y]  (uniform D) --------
        float srow[8];
        #pragma unroll
        for (int y = 0; y < 8; y++) {
            float s = 0.f;
            #pragma unroll
            for (int v = 0; v < 8; v++) s += k[v] * cD[v * 8 + y];
            srow[y] = s;
        }

        // ---------- T2: lane y now holds S[0..7][y] ----------
        transpose8(srow, r);

        // ---------- rec[x][y] = sum_u D[u][x] * S[u][y] + 128  (uniform) --
        float rc[8];
        #pragma unroll
        for (int x = 0; x < 8; x++) {
            float s = 0.f;
            #pragma unroll
            for (int u = 0; u < 8; u++) s += cD[u * 8 + x] * srow[u];
            rc[x] = s + 128.f;
        }

        // ---------- Write column y = r back (lanes consecutive) -----------
        if (bi < 16) {
            #pragma unroll
            for (int i = 0; i < 8; i++) sy[br0 + i][bc + r] = rc[i];
        } else if (bi < 20) {
            #pragma unroll
            for (int i = 0; i < 8; i++) scb2[br0 + i][bc + r] = rc[i];
        } else {
            #pragma unroll
            for (int i = 0; i < 8; i++) scr2[br0 + i][bc + r] = rc[i];
        }
    }
    __syncthreads();

    // ---------- Phase E: upsample chroma, YCbCr->RGB, clip, emit ----------
    // Re-load x (L1-resident from Phase A) instead of carrying 12 registers.
    {
        const float4 xr4 = *(const float4*)(in + base);
        const float4 xg4 = *(const float4*)(in + base + plane);
        const float4 xb4 = *(const float4*)(in + base + 2 * plane);
        const float xr[4] = {xr4.x, xr4.y, xr4.z, xr4.w};
        const float xg[4] = {xg4.x, xg4.y, xg4.z, xg4.w};
        const float xb[4] = {xb4.x, xb4.y, xb4.z, xb4.w};

        const float4 y4 = *(const float4*)&sy[row][col0];
        const float yv[4] = {y4.x, y4.y, y4.z, y4.w};

        float or_[4], og_[4], ob_[4];
        #pragma unroll
        for (int i = 0; i < 4; i++) {
            int cc = col0 + i;
            float Y   = yv[i];
            float cbm = scb2[row >> 1][cc >> 1] - 128.f;
            float crm = scr2[row >> 1][cc >> 1] - 128.f;
            float R2 = Y + 1.402f * crm;
            float G2 = Y - 0.344136f * cbm - 0.714136f * crm;
            float B2 = Y + 1.772f * cbm;
            R2 = fminf(fmaxf(R2, 0.f), 255.f) * (1.f / 255.f);
            G2 = fminf(fmaxf(G2, 0.f), 255.f) * (1.f / 255.f);
            B2 = fminf(fmaxf(B2, 0.f), 255.f) * (1.f / 255.f);
            // out = x + (jpeg - x), matching the reference's fp32 arithmetic
            or_[i] = xr[i] + (R2 - xr[i]);
            og_[i] = xg[i] + (G2 - xg[i]);
            ob_[i] = xb[i] + (B2 - xb[i]);
        }
        *(float4*)(out + base)             = make_float4(or_[0], or_[1], or_[2], or_[3]);
        *(float4*)(out + base + plane)     = make_float4(og_[0], og_[1], og_[2], og_[3]);
        *(float4*)(out + base + 2 * plane) = make_float4(ob_[0], ob_[1], ob_[2], ob_[3]);
    }
}

extern "C" void kernel_launch(void* const* d_in, const int* in_sizes, int n_in,
                              void* d_out, int out_size)
{
    const float* x = (const float*)d_in[0];
    float* out = (float*)d_out;
    dim3 grid(IMG / 32, IMG / 32, 16);   // (16,16,16) = 4096 CTAs
    diffjpeg_kernel<<<grid, 256>>>(x, out);
}